// round 1
// baseline (speedup 1.0000x reference)
#include <cuda_runtime.h>

#define NWIRES 11
#define SDIM   2048      // 2^11 amplitudes
#define PIX    1024
#define NB     1024      // batch
#define NLAY   4
#define NGATES (2*NLAY*NWIRES)   // 88 Rot matrices

// Precomputed Rot matrices: [gate][u00.re,u00.im,u01.re,u01.im,u10.re,u10.im,u11.re,u11.im]
__device__ float g_U[NGATES][8];

__device__ __forceinline__ float2 cmul(float2 a, float2 b) {
    return make_float2(a.x*b.x - a.y*b.y, a.x*b.y + a.y*b.x);
}
__device__ __forceinline__ float2 cadd(float2 a, float2 b) {
    return make_float2(a.x + b.x, a.y + b.y);
}

__global__ void precompute_gates(const float* __restrict__ w0,
                                 const float* __restrict__ w1) {
    int idx = blockIdx.x * blockDim.x + threadIdx.x;
    if (idx >= NGATES) return;
    const float PI_F = 3.14159265358979323846f;
    int k   = idx / (NLAY * NWIRES);
    int rem = idx % (NLAY * NWIRES);          // l*NWIRES + q
    const float* w = (k == 0) ? w0 : w1;      // layout (L, WIRES, 3)
    float phi   = PI_F * tanhf(w[rem * 3 + 0]);
    float theta = PI_F * tanhf(w[rem * 3 + 1]);
    float omega = PI_F * tanhf(w[rem * 3 + 2]);
    float c = cosf(0.5f * theta), s = sinf(0.5f * theta);
    float apo = 0.5f * (phi + omega);
    float bpo = 0.5f * (phi - omega);
    float are =  cosf(apo), aim = -sinf(apo);   // a = exp(-i*apo)
    float bre =  cosf(bpo), bim =  sinf(bpo);   // b = exp(+i*bpo)
    // u00 = a*c ; u01 = -b*s ; u10 = conj(b)*s ; u11 = conj(a)*c
    g_U[idx][0] =  are * c;  g_U[idx][1] =  aim * c;
    g_U[idx][2] = -bre * s;  g_U[idx][3] = -bim * s;
    g_U[idx][4] =  bre * s;  g_U[idx][5] = -bim * s;
    g_U[idx][6] =  are * c;  g_U[idx][7] = -aim * c;
}

__global__ __launch_bounds__(256)
void qsim_kernel(const float* __restrict__ x,
                 const float* __restrict__ y,
                 float* __restrict__ out) {
    __shared__ float2 st[SDIM];      // 16 KB state
    __shared__ float  red[8];

    const int b = blockIdx.x;
    const int t = threadIdx.x;
    const float* xb = x + (size_t)b * PIX;

    // ---- norm of x row (1024 elems, 256 threads) ----
    float ss = 0.0f;
    #pragma unroll
    for (int i = t; i < PIX; i += 256) { float v = xb[i]; ss += v * v; }
    #pragma unroll
    for (int o = 16; o > 0; o >>= 1) ss += __shfl_xor_sync(0xffffffffu, ss, o);
    if ((t & 31) == 0) red[t >> 5] = ss;
    __syncthreads();
    float tot = 0.0f;
    #pragma unroll
    for (int wdx = 0; wdx < 8; wdx++) tot += red[wdx];
    float inv = 1.0f / sqrtf(tot);

    // ---- amplitude embedding: even indices = emb, odd = 0 ----
    for (int i = t; i < PIX; i += 256) {
        st[2 * i]     = make_float2(xb[i] * inv, 0.0f);
        st[2 * i + 1] = make_float2(0.0f, 0.0f);
    }

    const float yhalf = 0.5f * y[b];
    const float yc = cosf(yhalf), ys = sinf(yhalf);
    __syncthreads();

    for (int k = 0; k < 2; k++) {
        // ---- RX(y) on wire 10 (bit 0): pairs (2p, 2p+1) ----
        // U = [[c, -i s],[-i s, c]]
        for (int p = t; p < PIX; p += 256) {
            float2 a0 = st[2 * p], a1 = st[2 * p + 1];
            st[2 * p]     = make_float2(yc * a0.x + ys * a1.y,
                                        yc * a0.y - ys * a1.x);
            st[2 * p + 1] = make_float2(ys * a0.y + yc * a1.x,
                                        yc * a1.y - ys * a0.x);
        }
        __syncthreads();

        for (int l = 0; l < NLAY; l++) {
            // ---- 11 single-qubit Rot gates ----
            for (int q = 0; q < NWIRES; q++) {
                const float* U = g_U[k * (NLAY * NWIRES) + l * NWIRES + q];
                const float2 u00 = make_float2(U[0], U[1]);
                const float2 u01 = make_float2(U[2], U[3]);
                const float2 u10 = make_float2(U[4], U[5]);
                const float2 u11 = make_float2(U[6], U[7]);
                const int tb = NWIRES - 1 - q;     // bit position of wire q
                const int m  = 1 << tb;
                #pragma unroll
                for (int pp = 0; pp < PIX / 256; pp++) {
                    int p  = t + pp * 256;
                    int i0 = ((p & ~(m - 1)) << 1) | (p & (m - 1));
                    int i1 = i0 | m;
                    float2 a0 = st[i0], a1 = st[i1];
                    st[i0] = cadd(cmul(u00, a0), cmul(u01, a1));
                    st[i1] = cadd(cmul(u10, a0), cmul(u11, a1));
                }
                __syncthreads();
            }

            // ---- fused CNOT chain: single permutation gather ----
            // forward: for q=0..10 apply CNOT(q,(q+r)%11) ; gather index applies
            // the CNOTs in REVERSE order to the destination index.
            const int r = l % (NWIRES - 1) + 1;
            float2 buf[SDIM / 256];
            #pragma unroll
            for (int jj = 0; jj < SDIM / 256; jj++) {
                int j = t + jj * 256;
                int src = j;
                #pragma unroll
                for (int q = NWIRES - 1; q >= 0; q--) {
                    int cb = NWIRES - 1 - q;
                    int tq = (q + r) % NWIRES;
                    int tbit = NWIRES - 1 - tq;
                    if ((src >> cb) & 1) src ^= (1 << tbit);
                }
                buf[jj] = st[src];
            }
            __syncthreads();
            #pragma unroll
            for (int jj = 0; jj < SDIM / 256; jj++) st[t + jj * 256] = buf[jj];
            __syncthreads();
        }
    }

    // ---- output: probs of even basis indices, * PIX, clipped to [0,1] ----
    float* ob = out + (size_t)b * PIX;
    for (int p = t; p < PIX; p += 256) {
        float2 a = st[2 * p];
        float v = (a.x * a.x + a.y * a.y) * (float)PIX;
        ob[p] = fminf(v, 1.0f);
    }
}

extern "C" void kernel_launch(void* const* d_in, const int* in_sizes, int n_in,
                              void* d_out, int out_size) {
    const float* x  = (const float*)d_in[0];   // (B,1,32,32)
    const float* y  = (const float*)d_in[1];   // (B,)
    const float* w0 = (const float*)d_in[2];   // (4,11,3)
    const float* w1 = (const float*)d_in[3];   // (4,11,3)
    float* out = (float*)d_out;                // (B,1,32,32)

    precompute_gates<<<1, 128>>>(w0, w1);
    qsim_kernel<<<NB, 256>>>(x, y, out);
}

// round 2
// speedup vs baseline: 2.0488x; 2.0488x over previous
#include <cuda_runtime.h>

#define NWIRES 11
#define SDIM   2048
#define PIX    1024
#define NB     1024
#define NLAY   4
#define NGATES (2*NLAY*NWIRES)   // 88

// Precomputed Rot matrices: g_U4[g][0]=(u00.re,u00.im,u01.re,u01.im), [1]=(u10,u11)
__device__ float4 g_U4[NGATES][2];

__global__ void precompute_gates(const float* __restrict__ w0,
                                 const float* __restrict__ w1) {
    int idx = blockIdx.x * blockDim.x + threadIdx.x;
    if (idx >= NGATES) return;
    const float PI_F = 3.14159265358979323846f;
    int k   = idx / (NLAY * NWIRES);
    int rem = idx % (NLAY * NWIRES);
    const float* w = (k == 0) ? w0 : w1;
    float phi   = PI_F * tanhf(w[rem * 3 + 0]);
    float theta = PI_F * tanhf(w[rem * 3 + 1]);
    float omega = PI_F * tanhf(w[rem * 3 + 2]);
    float c = cosf(0.5f * theta), s = sinf(0.5f * theta);
    float apo = 0.5f * (phi + omega);
    float bpo = 0.5f * (phi - omega);
    float are =  cosf(apo), aim = -sinf(apo);   // a = exp(-i*apo)
    float bre =  cosf(bpo), bim =  sinf(bpo);   // b = exp(+i*bpo)
    // u00=a*c ; u01=-b*s ; u10=conj(b)*s ; u11=conj(a)*c
    g_U4[idx][0] = make_float4( are*c,  aim*c, -bre*s, -bim*s);
    g_U4[idx][1] = make_float4( bre*s, -bim*s,  are*c, -aim*c);
}

// src index for the inverse of the CNOT chain with range r (gather form).
__device__ __forceinline__ int cinv_idx(int dst, int r) {
    int src = dst;
    for (int q = NWIRES - 1; q >= 0; q--) {
        int cb = NWIRES - 1 - q;
        int tq = q + r; if (tq >= NWIRES) tq -= NWIRES;
        int tbit = NWIRES - 1 - tq;
        src ^= ((src >> cb) & 1) << tbit;
    }
    return src;
}

// 2x2 complex gate on a register-index bit (stride in j).
__device__ __forceinline__ void reg_gate(float2 a[8], int stride,
                                         float2 u00, float2 u01,
                                         float2 u10, float2 u11) {
    #pragma unroll
    for (int j0 = 0; j0 < 8; j0++) {
        if (j0 & stride) continue;
        int j1 = j0 | stride;
        float2 a0 = a[j0], a1 = a[j1];
        a[j0].x = u00.x*a0.x - u00.y*a0.y + u01.x*a1.x - u01.y*a1.y;
        a[j0].y = u00.x*a0.y + u00.y*a0.x + u01.x*a1.y + u01.y*a1.x;
        a[j1].x = u10.x*a0.x - u10.y*a0.y + u11.x*a1.x - u11.y*a1.y;
        a[j1].y = u10.x*a0.y + u10.y*a0.x + u11.x*a1.y + u11.y*a1.x;
    }
}

// 2x2 complex gate on a lane bit via shfl butterfly.
__device__ __forceinline__ void shfl_gate(float2 a[8], int lane, int bit,
                                          float2 u00, float2 u01,
                                          float2 u10, float2 u11) {
    bool hi = (lane >> bit) & 1;
    float2 cs = hi ? u11 : u00;   // coefficient for own amplitude
    float2 co = hi ? u10 : u01;   // coefficient for partner amplitude
    int m = 1 << bit;
    #pragma unroll
    for (int j = 0; j < 8; j++) {
        float px = __shfl_xor_sync(0xffffffffu, a[j].x, m);
        float py = __shfl_xor_sync(0xffffffffu, a[j].y, m);
        float ax = a[j].x, ay = a[j].y;
        a[j].x = cs.x*ax - cs.y*ay + co.x*px - co.y*py;
        a[j].y = cs.x*ay + cs.y*ax + co.x*py + co.y*px;
    }
}

__device__ __forceinline__ void load_gate(int g, float2& u00, float2& u01,
                                          float2& u10, float2& u11) {
    float4 c0 = g_U4[g][0];
    float4 c1 = g_U4[g][1];
    u00 = make_float2(c0.x, c0.y); u01 = make_float2(c0.z, c0.w);
    u10 = make_float2(c1.x, c1.y); u11 = make_float2(c1.z, c1.w);
}

__global__ __launch_bounds__(256)
void qsim_kernel(const float* __restrict__ x,
                 const float* __restrict__ y,
                 float* __restrict__ out) {
    __shared__ float2 buf[2][SDIM];             // 32 KB double buffer
    __shared__ unsigned short preT[4][256];     // Cinv(t) per r
    __shared__ unsigned short preJ[4][8];       // Cinv(j<<8) per r
    __shared__ float red[8];

    const int b = blockIdx.x;
    const int t = threadIdx.x;
    const int lane = t & 31;
    const float* xb = x + (size_t)b * PIX;

    // ---- permutation tables (linear decomposition of Cinv) ----
    #pragma unroll
    for (int r = 1; r <= 4; r++) preT[r - 1][t] = (unsigned short)cinv_idx(t, r);
    if (t < 32) preJ[t >> 3][t & 7] = (unsigned short)cinv_idx((t & 7) << 8, (t >> 3) + 1);

    // ---- norm of x row ----
    float ss = 0.0f;
    #pragma unroll
    for (int i = t; i < PIX; i += 256) { float v = xb[i]; ss += v * v; }
    #pragma unroll
    for (int o = 16; o > 0; o >>= 1) ss += __shfl_xor_sync(0xffffffffu, ss, o);
    if (lane == 0) red[t >> 5] = ss;
    __syncthreads();
    float tot = 0.0f;
    #pragma unroll
    for (int wdx = 0; wdx < 8; wdx++) tot += red[wdx];
    float inv = 1.0f / sqrtf(tot);

    // ---- amplitude embedding into buf[0] ----
    #pragma unroll
    for (int i = t; i < PIX; i += 256) {
        buf[0][2 * i]     = make_float2(xb[i] * inv, 0.0f);
        buf[0][2 * i + 1] = make_float2(0.0f, 0.0f);
    }

    const float yhalf = 0.5f * y[b];
    const float yc = cosf(yhalf), ys = sinf(yhalf);
    __syncthreads();

    float2 a[8];
    int cur = 0;

    #pragma unroll 1
    for (int k = 0; k < 2; k++) {
        #pragma unroll 1
        for (int l = 0; l < NLAY; l++) {
            const int gbase = k * (NLAY * NWIRES) + l * NWIRES;
            // pending CNOT permutation from the PREVIOUS layer (folded into gather)
            const int pend = (k == 0 && l == 0) ? 0 : ((l == 0) ? 4 : l);

            // ================= PASS A =================
            // gather (applies pending perm); layout: idx = j*256 + t
            if (pend == 0) {
                #pragma unroll
                for (int j = 0; j < 8; j++) a[j] = buf[cur][(j << 8) | t];
            } else {
                const int base = preT[pend - 1][t];
                #pragma unroll
                for (int j = 0; j < 8; j++)
                    a[j] = buf[cur][base ^ preJ[pend - 1][j]];
            }

            // RX(y) on wire 10 (lane bit 0), before the layer's rotations
            if (l == 0) {
                shfl_gate(a, lane, 0,
                          make_float2(yc, 0.0f), make_float2(0.0f, -ys),
                          make_float2(0.0f, -ys), make_float2(yc, 0.0f));
            }

            // wires 6..10 -> lane bits 4..0
            {
                float2 u00, u01, u10, u11;
                load_gate(gbase + 6,  u00, u01, u10, u11); shfl_gate(a, lane, 4, u00, u01, u10, u11);
                load_gate(gbase + 7,  u00, u01, u10, u11); shfl_gate(a, lane, 3, u00, u01, u10, u11);
                load_gate(gbase + 8,  u00, u01, u10, u11); shfl_gate(a, lane, 2, u00, u01, u10, u11);
                load_gate(gbase + 9,  u00, u01, u10, u11); shfl_gate(a, lane, 1, u00, u01, u10, u11);
                load_gate(gbase + 10, u00, u01, u10, u11); shfl_gate(a, lane, 0, u00, u01, u10, u11);
            }
            // wires 0..2 -> register bits j2,j1,j0 (idx bits 10,9,8)
            {
                float2 u00, u01, u10, u11;
                load_gate(gbase + 0, u00, u01, u10, u11); reg_gate(a, 4, u00, u01, u10, u11);
                load_gate(gbase + 1, u00, u01, u10, u11); reg_gate(a, 2, u00, u01, u10, u11);
                load_gate(gbase + 2, u00, u01, u10, u11); reg_gate(a, 1, u00, u01, u10, u11);
            }

            const int nxt = cur ^ 1;
            #pragma unroll
            for (int j = 0; j < 8; j++) buf[nxt][(j << 8) | t] = a[j];
            __syncthreads();

            // ================= PASS B (in-place in buf[nxt]) =================
            // layout2: idx = (t{7:5})<<8 | g<<5 | t{4:0}  -> bits {7,6,5} in-register
            const int base2 = ((t & 0xE0) << 3) | (t & 31);
            #pragma unroll
            for (int g = 0; g < 8; g++) a[g] = buf[nxt][base2 | (g << 5)];
            {
                float2 u00, u01, u10, u11;
                load_gate(gbase + 3, u00, u01, u10, u11); reg_gate(a, 4, u00, u01, u10, u11);
                load_gate(gbase + 4, u00, u01, u10, u11); reg_gate(a, 2, u00, u01, u10, u11);
                load_gate(gbase + 5, u00, u01, u10, u11); reg_gate(a, 1, u00, u01, u10, u11);
            }
            #pragma unroll
            for (int g = 0; g < 8; g++) buf[nxt][base2 | (g << 5)] = a[g];

            cur = nxt;
            __syncthreads();
        }
    }

    // ---- output: pending perm r=4 folded into the final gather ----
    float* ob = out + (size_t)b * PIX;
    #pragma unroll
    for (int s = 0; s < 4; s++) {
        int p = t + s * 256;
        float2 v = buf[cur][cinv_idx(2 * p, 4)];
        float pr = (v.x * v.x + v.y * v.y) * (float)PIX;
        ob[p] = fminf(pr, 1.0f);
    }
}

extern "C" void kernel_launch(void* const* d_in, const int* in_sizes, int n_in,
                              void* d_out, int out_size) {
    const float* x  = (const float*)d_in[0];
    const float* y  = (const float*)d_in[1];
    const float* w0 = (const float*)d_in[2];
    const float* w1 = (const float*)d_in[3];
    float* out = (float*)d_out;

    precompute_gates<<<1, 128>>>(w0, w1);
    qsim_kernel<<<NB, 256>>>(x, y, out);
}

// round 3
// speedup vs baseline: 2.5464x; 1.2429x over previous
#include <cuda_runtime.h>

#define NWIRES 11
#define NLAY   4
#define NGATES 88
#define PIX    1024
#define NB     1024

typedef unsigned long long ull;

// Per gate: (c1,d1,c2,d2) = (u00.re, u00.im, u01.re, u01.im); SU(2): u10=(-c2,d2), u11=(c1,-d1)
__device__ float4 g_G[NGATES];

__global__ void precompute_gates(const float* __restrict__ w0,
                                 const float* __restrict__ w1) {
    int idx = blockIdx.x * blockDim.x + threadIdx.x;
    if (idx >= NGATES) return;
    const float PI_F = 3.14159265358979323846f;
    int k = idx / 44, rem = idx % 44;
    const float* w = (k == 0) ? w0 : w1;
    float phi   = PI_F * tanhf(w[rem * 3 + 0]);
    float theta = PI_F * tanhf(w[rem * 3 + 1]);
    float omega = PI_F * tanhf(w[rem * 3 + 2]);
    float c = cosf(0.5f * theta), s = sinf(0.5f * theta);
    float apo = 0.5f * (phi + omega), bpo = 0.5f * (phi - omega);
    float are = cosf(apo), aim = -sinf(apo);   // a = exp(-i*apo)
    float bre = cosf(bpo), bim = sinf(bpo);    // b = exp(+i*bpo)
    g_G[idx] = make_float4(are * c, aim * c, -bre * s, -bim * s);
}

// inverse CNOT-chain permutation (gather form), identical to validated round-2 logic
__device__ __forceinline__ int cinv_idx(int dst, int r) {
    int src = dst;
    for (int q = NWIRES - 1; q >= 0; q--) {
        int cb = NWIRES - 1 - q;
        int tq = q + r; if (tq >= NWIRES) tq -= NWIRES;
        int tbit = NWIRES - 1 - tq;
        src ^= ((src >> cb) & 1) << tbit;
    }
    return src;
}
// amp index s -> float offset of its re part in the float4-pair smem layout
__device__ __forceinline__ int fmap(int s) { return ((s >> 1) << 2) | (s & 1); }

// ---- packed f32x2 helpers ----
__device__ __forceinline__ ull pk(float lo, float hi) {
    ull r; asm("mov.b64 %0,{%1,%2};" : "=l"(r) : "f"(lo), "f"(hi)); return r;
}
__device__ __forceinline__ void upk(ull v, float& lo, float& hi) {
    asm("mov.b64 {%0,%1},%2;" : "=f"(lo), "=f"(hi) : "l"(v));
}
__device__ __forceinline__ ull dup2(float v) { return pk(v, v); }
__device__ __forceinline__ ull m2(ull a, ull b) {
    ull d; asm("mul.rn.f32x2 %0,%1,%2;" : "=l"(d) : "l"(a), "l"(b)); return d;
}
__device__ __forceinline__ ull f2(ull a, ull b, ull c) {
    ull d; asm("fma.rn.f32x2 %0,%1,%2,%3;" : "=l"(d) : "l"(a), "l"(b), "l"(c)); return d;
}

// SU(2) gate on an inter-register bit (broadcast packed form). flip swaps 0/1 roles.
__device__ __forceinline__ void gate_reg(ull aRe[8], ull aIm[8], float4 g,
                                         int stride, bool flip) {
    float c1 = g.x, d1 = flip ? -g.y : g.y, c2 = flip ? -g.z : g.z, d2 = g.w;
    ull C1 = dup2(c1), D1 = dup2(d1), ND1 = dup2(-d1);
    ull C2 = dup2(c2), NC2 = dup2(-c2), D2 = dup2(d2), ND2 = dup2(-d2);
    #pragma unroll
    for (int j0 = 0; j0 < 8; j0++) {
        if (j0 & stride) continue;
        int j1 = j0 | stride;
        ull A0r = aRe[j0], A0i = aIm[j0], A1r = aRe[j1], A1i = aIm[j1];
        ull o0r = f2(ND2, A1i, f2(C2, A1r, f2(ND1, A0i, m2(C1, A0r))));
        ull o0i = f2(C2,  A1i, f2(D2, A1r, f2(C1,  A0i, m2(D1, A0r))));
        ull o1r = f2(D1,  A1i, f2(C1, A1r, f2(ND2, A0i, m2(NC2, A0r))));
        ull o1i = f2(C1,  A1i, f2(ND1,A1r, f2(NC2, A0i, m2(D2,  A0r))));
        aRe[j0] = o0r; aIm[j0] = o0i; aRe[j1] = o1r; aIm[j1] = o1i;
    }
}

// SU(2) gate on lane bit 0 (partner via shfl)
__device__ __forceinline__ void gate_shfl(ull aRe[8], ull aIm[8], float4 g, int hi) {
    float sd1 = hi ? -g.y : g.y;     // csy
    float sc2 = hi ? -g.z : g.z;     // cox
    ull CSX = dup2(g.x), CSY = dup2(sd1), NCSY = dup2(-sd1);
    ull COX = dup2(sc2), COY = dup2(g.w), NCOY = dup2(-g.w);
    #pragma unroll
    for (int j = 0; j < 8; j++) {
        ull Pr = __shfl_xor_sync(0xffffffffu, aRe[j], 1);
        ull Pi = __shfl_xor_sync(0xffffffffu, aIm[j], 1);
        ull Or = f2(NCOY, Pi, f2(COX, Pr, f2(NCSY, aIm[j], m2(CSX, aRe[j]))));
        ull Oi = f2(COX,  Pi, f2(COY, Pr, f2(CSX,  aIm[j], m2(CSY, aRe[j]))));
        aRe[j] = Or; aIm[j] = Oi;
    }
}

// SU(2) gate on the packing bit (intra-register butterfly via swapped halves)
__device__ __forceinline__ void gate_intra(ull aRe[8], ull aIm[8], float4 g) {
    float c1 = g.x, d1 = g.y, c2 = g.z, d2 = g.w;
    ull K1 = dup2(c1), K2 = pk(c2, -c2), K3 = pk(-d1, d1), K4 = dup2(-d2);
    ull K5 = pk(d1, -d1), K6 = dup2(d2);
    #pragma unroll
    for (int j = 0; j < 8; j++) {
        float rl, rh, il, ih;
        upk(aRe[j], rl, rh); upk(aIm[j], il, ih);
        ull Sr = pk(rh, rl), Si = pk(ih, il);
        ull Or = f2(K4, Si, f2(K3, aIm[j], f2(K2, Sr, m2(K1, aRe[j]))));
        ull Oi = f2(K2, Si, f2(K1, aIm[j], f2(K6, Sr, m2(K5, aRe[j]))));
        aRe[j] = Or; aIm[j] = Oi;
    }
}

__global__ __launch_bounds__(128)
void qsim_kernel(const float* __restrict__ x,
                 const float* __restrict__ y,
                 float* __restrict__ out) {
    __shared__ float4 sp4[1024];   // pair P: (re0,re1,im0,im1)  -- 16 KB
    __shared__ int fT[4][128];
    __shared__ int fR[4][8];
    __shared__ int fW[4];
    __shared__ float red[4];
    float* smf = (float*)sp4;

    const int b = blockIdx.x, t = threadIdx.x;
    const float* xb = x + (size_t)b * PIX;

    // ---- permutation tables (address-space, XOR-composable) ----
    for (int i2 = t; i2 < 512; i2 += 128) {
        int rr = i2 >> 7, tt = i2 & 127;
        fT[rr][tt] = fmap(cinv_idx(tt << 1, rr + 1));
    }
    if (t < 32) fR[t >> 3][t & 7] = fmap(cinv_idx((t & 7) << 8, (t >> 3) + 1));
    if (t < 4)  fW[t] = fmap(cinv_idx(1, t + 1));

    // ---- norm ----
    float ss = 0.0f;
    #pragma unroll
    for (int i = t; i < PIX; i += 128) { float v = xb[i]; ss += v * v; }
    #pragma unroll
    for (int o = 16; o > 0; o >>= 1) ss += __shfl_xor_sync(0xffffffffu, ss, o);
    if ((t & 31) == 0) red[t >> 5] = ss;
    __syncthreads();
    float inv = 1.0f / sqrtf(red[0] + red[1] + red[2] + red[3]);

    // ---- embedding: pair P = (emb[P], 0 | 0, 0) ----
    #pragma unroll
    for (int s8 = 0; s8 < 8; s8++) {
        int P = t + (s8 << 7);
        sp4[P] = make_float4(xb[P] * inv, 0.0f, 0.0f, 0.0f);
    }
    const float yhalf = 0.5f * y[b];
    const float yc = cosf(yhalf), ys = sinf(yhalf);
    __syncthreads();

    ull aRe[8], aIm[8];
    const int t31 = (t >> 1) & 7;
    const int B3x = ((t >> 1) << 4) | (t31 << 1) | (t & 1);
    const int b2  = ((t >> 4) << 7) | (t & 15);

    #pragma unroll 1
    for (int k = 0; k < 2; k++) {
        #pragma unroll 1
        for (int l = 0; l < NLAY; l++) {
            const int gbase = k * 44 + l * 11;
            const int pend = (k == 0 && l == 0) ? 0 : ((l == 0) ? 4 : l);

            // ===== layout 1: reg bits = i[10:8] (wires 0,1,2); perm folded into gather =====
            if (pend == 0) {
                #pragma unroll
                for (int r = 0; r < 8; r++) {
                    float4 v = sp4[(r << 7) | t];
                    aRe[r] = pk(v.x, v.y); aIm[r] = pk(v.z, v.w);
                }
            } else {
                const int base = fT[pend - 1][t], wv = fW[pend - 1];
                #pragma unroll
                for (int r = 0; r < 8; r++) {
                    int A0 = base ^ fR[pend - 1][r];
                    int A1 = A0 ^ wv;
                    aRe[r] = pk(smf[A0], smf[A1]);
                    aIm[r] = pk(smf[A0 + 2], smf[A1 + 2]);
                }
            }
            gate_reg(aRe, aIm, g_G[gbase + 0], 4, false);
            gate_reg(aRe, aIm, g_G[gbase + 1], 2, false);
            gate_reg(aRe, aIm, g_G[gbase + 2], 1, false);
            #pragma unroll
            for (int r = 0; r < 8; r++) {
                float rl, rh, il, ih;
                upk(aRe[r], rl, rh); upk(aIm[r], il, ih);
                sp4[(r << 7) | t] = make_float4(rl, rh, il, ih);
            }
            __syncthreads();

            // ===== layout 2: reg bits = i[7:5] (wires 3,4,5) =====
            #pragma unroll
            for (int r = 0; r < 8; r++) {
                float4 v = sp4[b2 | (r << 4)];
                aRe[r] = pk(v.x, v.y); aIm[r] = pk(v.z, v.w);
            }
            gate_reg(aRe, aIm, g_G[gbase + 3], 4, false);
            gate_reg(aRe, aIm, g_G[gbase + 4], 2, false);
            gate_reg(aRe, aIm, g_G[gbase + 5], 1, false);
            #pragma unroll
            for (int r = 0; r < 8; r++) {
                float rl, rh, il, ih;
                upk(aRe[r], rl, rh); upk(aIm[r], il, ih);
                sp4[b2 | (r << 4)] = make_float4(rl, rh, il, ih);
            }
            __syncthreads();

            // ===== layout 3: reg bits = i[4:2] (wires 6,7,8) XOR-relabeled; bit1 shfl; bit0 intra =====
            #pragma unroll
            for (int u = 0; u < 8; u++) {
                float4 v = sp4[B3x ^ (u << 1)];
                aRe[u] = pk(v.x, v.y); aIm[u] = pk(v.z, v.w);
            }
            gate_reg(aRe, aIm, g_G[gbase + 6], 4, (t31 >> 2) & 1);
            gate_reg(aRe, aIm, g_G[gbase + 7], 2, (t31 >> 1) & 1);
            gate_reg(aRe, aIm, g_G[gbase + 8], 1, t31 & 1);
            gate_shfl(aRe, aIm, g_G[gbase + 9], t & 1);
            {
                float4 G = g_G[gbase + 10];
                if (l == 0) {   // fuse RX(y): F = Rot * RX
                    float c1 = G.x, d1 = G.y, c2 = G.z, d2 = G.w;
                    G = make_float4(c1 * yc + d2 * ys, d1 * yc - c2 * ys,
                                    d1 * ys + c2 * yc, -c1 * ys + d2 * yc);
                }
                gate_intra(aRe, aIm, G);
            }
            #pragma unroll
            for (int u = 0; u < 8; u++) {
                float rl, rh, il, ih;
                upk(aRe[u], rl, rh); upk(aIm[u], il, ih);
                sp4[B3x ^ (u << 1)] = make_float4(rl, rh, il, ih);
            }
            __syncthreads();
        }
    }

    // ---- epilogue: final perm (r=4) folded; probs of even basis states ----
    float* ob = out + (size_t)b * PIX;
    const int baseo = fT[3][t];
    #pragma unroll
    for (int s8 = 0; s8 < 8; s8++) {
        int addr = baseo ^ fR[3][s8];
        float re = smf[addr], im = smf[addr + 2];
        float pr = (re * re + im * im) * 1024.0f;
        ob[(s8 << 7) + t] = fminf(pr, 1.0f);
    }
}

extern "C" void kernel_launch(void* const* d_in, const int* in_sizes, int n_in,
                              void* d_out, int out_size) {
    const float* x  = (const float*)d_in[0];
    const float* y  = (const float*)d_in[1];
    const float* w0 = (const float*)d_in[2];
    const float* w1 = (const float*)d_in[3];
    float* out = (float*)d_out;

    precompute_gates<<<1, 128>>>(w0, w1);
    qsim_kernel<<<NB, 128>>>(x, y, out);
}